// round 14
// baseline (speedup 1.0000x reference)
#include <cuda_runtime.h>

// 15x15 separable Gaussian, 8192x8192 f32, reflect pad, stride 1.
// Fused separable conv (R11 base + streamed run=16 horizontal pass):
//   phase 1: vertical, packed f32x2 symmetric taps, register sliding window,
//            global -> smem vbuf. Interior CTAs use a bumped row pointer;
//            border CTAs use the refl path.
//   phase 2: horizontal, 16-output runs streamed in two halves (peak live
//            window ~31 floats, no spills), FFMA-imm, 4-row interleaved task
//            map -> conflict-free LDS.128 (VSTRIDE=132: addr mod 128 =
//            64c + 16(u&3) + 64q spans {0,16,...,112} per 8-lane phase).
// Coefficients hardcoded (problem-fixed Gaussian sigma=3, 15 taps);
// rel_err ~2.4e-7 verified across rounds.

#define IMW 8192
#define IMH 8192
#define TX  112          // output tile width (128 vbuf cols incl. 8+8 halo)
#define TY  80           // output tile height
#define VSTRIDE 132      // floats; 132*4=528 B, 528 % 128 == 16
#define NSX 74           // ceil(8192/112)
#define NSY 103          // ceil(8192/80)

static __device__ __forceinline__ int refl(int i) {
    i = (i < 0) ? -i : i;
    return (i >= IMW) ? (2 * IMW - 2 - i) : i;
}

__device__ __forceinline__ float2 ffma2(float2 a, float2 b, float2 c) {
    unsigned long long ua = *reinterpret_cast<unsigned long long*>(&a);
    unsigned long long ub = *reinterpret_cast<unsigned long long*>(&b);
    unsigned long long uc = *reinterpret_cast<unsigned long long*>(&c);
    unsigned long long ud;
    asm("fma.rn.f32x2 %0, %1, %2, %3;" : "=l"(ud) : "l"(ua), "l"(ub), "l"(uc));
    return *reinterpret_cast<float2*>(&ud);
}

__device__ __forceinline__ float2 fmul2(float2 a, float2 b) {
    unsigned long long ua = *reinterpret_cast<unsigned long long*>(&a);
    unsigned long long ub = *reinterpret_cast<unsigned long long*>(&b);
    unsigned long long ud;
    asm("mul.rn.f32x2 %0, %1, %2;" : "=l"(ud) : "l"(ua), "l"(ub));
    return *reinterpret_cast<float2*>(&ud);
}

__device__ __forceinline__ float2 fadd2(float2 a, float2 b) {
    unsigned long long ua = *reinterpret_cast<unsigned long long*>(&a);
    unsigned long long ub = *reinterpret_cast<unsigned long long*>(&b);
    unsigned long long ud;
    asm("add.rn.f32x2 %0, %1, %2;" : "=l"(ud) : "l"(ua), "l"(ub));
    return *reinterpret_cast<float2*>(&ud);
}

__global__ __launch_bounds__(256, 3)
void gauss_sep_kernel(const float* __restrict__ img,
                      float* __restrict__ out) {
    // normalized 1-D Gaussian, sigma=3, 15 taps (fp32)
    const float KC[15] = {
        0.00884695f, 0.01821590f, 0.03356240f, 0.05533503f,
        0.08163801f, 0.10777792f, 0.12732457f, 0.13459834f,
        0.12732457f, 0.10777792f, 0.08163801f, 0.05533503f,
        0.03356240f, 0.01821590f, 0.00884695f };

    __shared__ __align__(16) float vbuf[TY * VSTRIDE];   // 42.24 KB

    const int tid = threadIdx.x;
    const int bx = blockIdx.x;
    const int by = blockIdx.y;

    // ---- phase 1: vertical conv (packed f32x2, symmetric), global -> vbuf ----
    {
        const int pc = tid & 63;        // float2 column 0..63 (128 vbuf cols)
        const int g  = tid >> 6;        // y-group 0..3 (20 vbuf rows each)
        const int gxp = bx * TX - 8 + 2 * pc;          // global col of pair
        const int gy0 = by * TY + 20 * g;              // first output row of group

        float2 kyv[8];
        #pragma unroll
        for (int i = 0; i < 8; i++) kyv[i] = make_float2(KC[i], KC[i]);

        float2 win[15];

        const bool interior = (bx > 0) && (bx < NSX - 1) && (by > 0) && (by < NSY - 1);

        if (interior) {
            // fast path: no reflection anywhere; bumped row pointer
            const float* rp = img + (size_t)(gy0 - 7) * IMW + gxp;
            #pragma unroll
            for (int i = 0; i < 14; i++) {
                win[i] = *reinterpret_cast<const float2*>(rp);
                rp += IMW;
            }
            #pragma unroll
            for (int s = 0; s < 20; s++) {
                const float2 nv = *reinterpret_cast<const float2*>(rp);
                rp += IMW;
                win[(14 + s) % 15] = nv;

                float2 acc = fmul2(kyv[7], win[(s + 7) % 15]);
                #pragma unroll
                for (int i = 0; i < 7; i++)
                    acc = ffma2(kyv[i],
                                fadd2(win[(s + i) % 15], win[(s + 14 - i) % 15]),
                                acc);

                *reinterpret_cast<float2*>(&vbuf[(20 * g + s) * VSTRIDE + 2 * pc]) = acc;
            }
        } else {
            const bool xok = (gxp >= 0) && (gxp + 1 < IMW);
            const int rx0 = refl(gxp);
            const int rx1 = refl(gxp + 1);

            #pragma unroll
            for (int i = 0; i < 14; i++) {
                const int ry = refl(gy0 - 7 + i);
                const float* rp = img + (size_t)ry * IMW;
                if (xok) {
                    win[i] = *reinterpret_cast<const float2*>(rp + gxp);
                } else {
                    win[i].x = rp[rx0]; win[i].y = rp[rx1];
                }
            }
            #pragma unroll
            for (int s = 0; s < 20; s++) {
                const int ry = refl(gy0 + s + 7);
                const float* rp = img + (size_t)ry * IMW;
                float2 nv;
                if (xok) {
                    nv = *reinterpret_cast<const float2*>(rp + gxp);
                } else {
                    nv.x = rp[rx0]; nv.y = rp[rx1];
                }
                win[(14 + s) % 15] = nv;

                float2 acc = fmul2(kyv[7], win[(s + 7) % 15]);
                #pragma unroll
                for (int i = 0; i < 7; i++)
                    acc = ffma2(kyv[i],
                                fadd2(win[(s + i) % 15], win[(s + 14 - i) % 15]),
                                acc);

                *reinterpret_cast<float2*>(&vbuf[(20 * g + s) * VSTRIDE + 2 * pc]) = acc;
            }
        }
    }
    __syncthreads();

    // ---- phase 2: horizontal conv, streamed 16-output runs, FFMA-imm ----
    // 7 runs/row * 80 rows = 560 tasks. 4-row interleave: conflict-free
    // LDS.128 quarter-phases. Each task: 6 LDS.128 -> 8 outputs -> store ->
    // 2 LDS.128 -> 8 outputs -> store (peak live window ~31 floats).
    {
        const int X0  = bx * TX;
        const int gyb = by * TY;

        for (int t = tid; t < 560; t += 256) {
            const int c   = t / 28;              // 4-row group 0..19
            const int u   = t - c * 28;
            const int row = 4 * c + (u & 3);     // 0..79
            const int q   = u >> 2;              // run 0..6

            const float* vp = &vbuf[row * VSTRIDE + q * 16];
            const int gy = gyb + row;
            const int gx = X0 + 16 * q;
            const bool yok = (gy < IMH);
            float* op = out + (size_t)gy * IMW + gx;

            float w[32];
            // first half: w[0..23]
            #pragma unroll
            for (int j = 0; j < 6; j++) {
                const float4 f = *reinterpret_cast<const float4*>(vp + 4 * j);
                w[4 * j]     = f.x;
                w[4 * j + 1] = f.y;
                w[4 * j + 2] = f.z;
                w[4 * j + 3] = f.w;
            }

            // outputs k=0..7 use w[1+k .. 15+k] (max w[22])
            {
                float o[8];
                #pragma unroll
                for (int k = 0; k < 8; k++) o[k] = KC[0] * w[1 + k];
                #pragma unroll
                for (int i = 1; i < 15; i++) {
                    #pragma unroll
                    for (int k = 0; k < 8; k++)
                        o[k] = fmaf(KC[i], w[1 + k + i], o[k]);
                }
                if (yok && gx + 3 < IMW)
                    *reinterpret_cast<float4*>(op) =
                        make_float4(o[0], o[1], o[2], o[3]);
                if (yok && gx + 7 < IMW)
                    *reinterpret_cast<float4*>(op + 4) =
                        make_float4(o[4], o[5], o[6], o[7]);
            }

            // second half: w[24..31]
            #pragma unroll
            for (int j = 6; j < 8; j++) {
                const float4 f = *reinterpret_cast<const float4*>(vp + 4 * j);
                w[4 * j]     = f.x;
                w[4 * j + 1] = f.y;
                w[4 * j + 2] = f.z;
                w[4 * j + 3] = f.w;
            }

            // outputs k=8..15 use w[9+k' .. 23+k'] (k'=k-8, max w[30])
            {
                float o[8];
                #pragma unroll
                for (int k = 0; k < 8; k++) o[k] = KC[0] * w[9 + k];
                #pragma unroll
                for (int i = 1; i < 15; i++) {
                    #pragma unroll
                    for (int k = 0; k < 8; k++)
                        o[k] = fmaf(KC[i], w[9 + k + i], o[k]);
                }
                if (yok && gx + 11 < IMW)
                    *reinterpret_cast<float4*>(op + 8) =
                        make_float4(o[0], o[1], o[2], o[3]);
                if (yok && gx + 15 < IMW)
                    *reinterpret_cast<float4*>(op + 12) =
                        make_float4(o[4], o[5], o[6], o[7]);
            }
        }
    }
}

extern "C" void kernel_launch(void* const* d_in, const int* in_sizes, int n_in,
                              void* d_out, int out_size) {
    const float* img = (const float*)d_in[0];
    float* out = (float*)d_out;

    dim3 grid(NSX, NSY);
    gauss_sep_kernel<<<grid, 256>>>(img, out);
}

// round 16
// speedup vs baseline: 1.0707x; 1.0707x over previous
#include <cuda_runtime.h>

// 15x15 separable Gaussian, 8192x8192 f32, reflect pad, stride 1.
// Fused separable conv (R11 phase-1 + sliding-window horizontal pass):
//   phase 1: vertical, packed f32x2 symmetric taps, register sliding window,
//            global -> smem vbuf. Interior CTAs use a bumped row pointer;
//            border CTAs use the refl path. TY=64 (4 groups x 16 rows).
//   phase 2: horizontal, 28-output row segments, 5xfloat4 rotating register
//            window (20 floats live), FFMA-imm. 64 rows x 4 segs = 256 tasks
//            = exactly 1 per thread. VSTRIDE=136 (544 B == 32 mod 128) +
//            (row,seg) lane map -> every 8-lane LDS.128 phase hits all 8
//            16B banks (conflict-free).
// Coefficients hardcoded (problem-fixed Gaussian sigma=3, 15 taps);
// rel_err ~2.4e-7 verified across rounds.

#define IMW 8192
#define IMH 8192
#define TX  112          // output tile width (128 vbuf cols incl. 8+8 halo)
#define TY  64           // output tile height (4 groups x 16 rows)
#define VSTRIDE 136      // floats; 136*4=544 B, 544 % 128 == 32
#define NSX 74           // ceil(8192/112)
#define NSY 128          // 8192/64 exact

static __device__ __forceinline__ int refl(int i) {
    i = (i < 0) ? -i : i;
    return (i >= IMW) ? (2 * IMW - 2 - i) : i;
}

__device__ __forceinline__ float2 ffma2(float2 a, float2 b, float2 c) {
    unsigned long long ua = *reinterpret_cast<unsigned long long*>(&a);
    unsigned long long ub = *reinterpret_cast<unsigned long long*>(&b);
    unsigned long long uc = *reinterpret_cast<unsigned long long*>(&c);
    unsigned long long ud;
    asm("fma.rn.f32x2 %0, %1, %2, %3;" : "=l"(ud) : "l"(ua), "l"(ub), "l"(uc));
    return *reinterpret_cast<float2*>(&ud);
}

__device__ __forceinline__ float2 fmul2(float2 a, float2 b) {
    unsigned long long ua = *reinterpret_cast<unsigned long long*>(&a);
    unsigned long long ub = *reinterpret_cast<unsigned long long*>(&b);
    unsigned long long ud;
    asm("mul.rn.f32x2 %0, %1, %2;" : "=l"(ud) : "l"(ua), "l"(ub));
    return *reinterpret_cast<float2*>(&ud);
}

__device__ __forceinline__ float2 fadd2(float2 a, float2 b) {
    unsigned long long ua = *reinterpret_cast<unsigned long long*>(&a);
    unsigned long long ub = *reinterpret_cast<unsigned long long*>(&b);
    unsigned long long ud;
    asm("add.rn.f32x2 %0, %1, %2;" : "=l"(ud) : "l"(ua), "l"(ub));
    return *reinterpret_cast<float2*>(&ud);
}

__global__ __launch_bounds__(256, 3)
void gauss_sep_kernel(const float* __restrict__ img,
                      float* __restrict__ out) {
    // normalized 1-D Gaussian, sigma=3, 15 taps (fp32)
    const float KC[15] = {
        0.00884695f, 0.01821590f, 0.03356240f, 0.05533503f,
        0.08163801f, 0.10777792f, 0.12732457f, 0.13459834f,
        0.12732457f, 0.10777792f, 0.08163801f, 0.05533503f,
        0.03356240f, 0.01821590f, 0.00884695f };

    __shared__ __align__(16) float vbuf[TY * VSTRIDE];   // 34.8 KB

    const int tid = threadIdx.x;
    const int bx = blockIdx.x;
    const int by = blockIdx.y;

    // ---- phase 1: vertical conv (packed f32x2, symmetric), global -> vbuf ----
    {
        const int pc = tid & 63;        // float2 column 0..63 (128 vbuf cols)
        const int g  = tid >> 6;        // y-group 0..3 (16 vbuf rows each)
        const int gxp = bx * TX - 8 + 2 * pc;          // global col of pair
        const int gy0 = by * TY + 16 * g;              // first output row of group

        float2 kyv[8];
        #pragma unroll
        for (int i = 0; i < 8; i++) kyv[i] = make_float2(KC[i], KC[i]);

        float2 win[15];

        const bool interior = (bx > 0) && (bx < NSX - 1) && (by > 0) && (by < NSY - 1);

        if (interior) {
            // fast path: no reflection anywhere; bumped row pointer
            const float* rp = img + (size_t)(gy0 - 7) * IMW + gxp;
            #pragma unroll
            for (int i = 0; i < 14; i++) {
                win[i] = *reinterpret_cast<const float2*>(rp);
                rp += IMW;
            }
            #pragma unroll
            for (int s = 0; s < 16; s++) {
                const float2 nv = *reinterpret_cast<const float2*>(rp);
                rp += IMW;
                win[(14 + s) % 15] = nv;

                float2 acc = fmul2(kyv[7], win[(s + 7) % 15]);
                #pragma unroll
                for (int i = 0; i < 7; i++)
                    acc = ffma2(kyv[i],
                                fadd2(win[(s + i) % 15], win[(s + 14 - i) % 15]),
                                acc);

                *reinterpret_cast<float2*>(&vbuf[(16 * g + s) * VSTRIDE + 2 * pc]) = acc;
            }
        } else {
            const bool xok = (gxp >= 0) && (gxp + 1 < IMW);
            const int rx0 = refl(gxp);
            const int rx1 = refl(gxp + 1);

            #pragma unroll
            for (int i = 0; i < 14; i++) {
                const int ry = refl(gy0 - 7 + i);
                const float* rp = img + (size_t)ry * IMW;
                if (xok) {
                    win[i] = *reinterpret_cast<const float2*>(rp + gxp);
                } else {
                    win[i].x = rp[rx0]; win[i].y = rp[rx1];
                }
            }
            #pragma unroll
            for (int s = 0; s < 16; s++) {
                const int ry = refl(gy0 + s + 7);
                const float* rp = img + (size_t)ry * IMW;
                float2 nv;
                if (xok) {
                    nv = *reinterpret_cast<const float2*>(rp + gxp);
                } else {
                    nv.x = rp[rx0]; nv.y = rp[rx1];
                }
                win[(14 + s) % 15] = nv;

                float2 acc = fmul2(kyv[7], win[(s + 7) % 15]);
                #pragma unroll
                for (int i = 0; i < 7; i++)
                    acc = ffma2(kyv[i],
                                fadd2(win[(s + i) % 15], win[(s + 14 - i) % 15]),
                                acc);

                *reinterpret_cast<float2*>(&vbuf[(16 * g + s) * VSTRIDE + 2 * pc]) = acc;
            }
        }
    }
    __syncthreads();

    // ---- phase 2: horizontal conv, sliding register window, vbuf -> out ----
    // 256 tasks (64 rows x 4 segments of 28 outputs), exactly 1 per thread.
    // Per task: 4 warm-up LDS.128, then 7x { LDS.128 -> 4 outputs -> STG.128 }.
    {
        const int X0  = bx * TX;
        const int gyb = by * TY;
        const bool xedge = (bx == NSX - 1);

        const int u   = tid & 7;
        const int c   = tid >> 3;                 // 0..31
        const int row = 4 * (c & 15) + (u & 3);   // 0..63
        const int seg = 2 * (c >> 4) + (u >> 2);  // 0..3

        const float* vp = &vbuf[row * VSTRIDE + seg * 28];
        const int gx0 = X0 + seg * 28;
        float* op = out + (size_t)(gyb + row) * IMW + gx0;

        float4 wq[5];
        #pragma unroll
        for (int m = 0; m < 4; m++)
            wq[m] = *reinterpret_cast<const float4*>(vp + 4 * m);

        #pragma unroll
        for (int j = 0; j < 7; j++) {
            wq[(j + 4) % 5] = *reinterpret_cast<const float4*>(vp + 4 * (j + 4));

            // window w[0..19] = vbuf cols (seg*28 + 4j) .. (+19)
            float w[20];
            #pragma unroll
            for (int p = 0; p < 5; p++) {
                const float4 f = wq[(j + p) % 5];
                w[4 * p]     = f.x;
                w[4 * p + 1] = f.y;
                w[4 * p + 2] = f.z;
                w[4 * p + 3] = f.w;
            }

            // outputs d=0..3 at tile col seg*28+4j+d use w[d+1 .. d+15]
            float o[4];
            #pragma unroll
            for (int d = 0; d < 4; d++) o[d] = KC[0] * w[d + 1];
            #pragma unroll
            for (int i = 1; i < 15; i++) {
                #pragma unroll
                for (int d = 0; d < 4; d++)
                    o[d] = fmaf(KC[i], w[d + 1 + i], o[d]);
            }

            if (!xedge || gx0 + 4 * j + 3 < IMW) {
                *reinterpret_cast<float4*>(op + 4 * j) =
                    make_float4(o[0], o[1], o[2], o[3]);
            }
        }
    }
}

extern "C" void kernel_launch(void* const* d_in, const int* in_sizes, int n_in,
                              void* d_out, int out_size) {
    const float* img = (const float*)d_in[0];
    float* out = (float*)d_out;

    dim3 grid(NSX, NSY);
    gauss_sep_kernel<<<grid, 256>>>(img, out);
}